// round 1
// baseline (speedup 1.0000x reference)
#include <cuda_runtime.h>
#include <cuda_bf16.h>

// Shapes (hardcoded from reference): B=512, T=128, N=128, H=256
#define BB 512
#define TT 128
#define NN 128
#define HH 256

// Scratch (device globals; allocation-free per harness rules)
__device__ float g_xW[TT * BB * HH];    // [s][b][h]  64 MB
__device__ float g_Hs[TT * BB * HH];    // [s][b][h]  64 MB
__device__ float g_Q[TT * BB * TT];     // [s][b][t]  32 MB
__device__ float g_preT[BB * TT * NN];  // [b][t][n]  32 MB

__device__ __forceinline__ float tanh_fast(float x) {
    float y;
    asm("tanh.approx.f32 %0, %1;" : "=f"(y) : "f"(x));
    return y;
}

// ---------------------------------------------------------------------------
// K1: preT[b][t][n] = sum_tau W1[tau][t] * data[b][tau][n] + b1[t]
// One CTA per b. smem: W1 (64KB) + data_b (64KB). 16x16 threads, 8x8 reg tile.
// ---------------------------------------------------------------------------
__global__ __launch_bounds__(256) void k_pre(const float* __restrict__ data,
                                             const float* __restrict__ W1,
                                             const float* __restrict__ b1) {
    extern __shared__ float sm[];
    float* sW = sm;          // [128][128] sW[tau][t]
    float* sD = sm + 16384;  // [128][128] sD[tau][n]
    int b = blockIdx.x;
    int tid = threadIdx.x;

    const float4* gW = (const float4*)W1;
    const float4* gD = (const float4*)(data + (size_t)b * (TT * NN));
    for (int i = tid; i < 4096; i += 256) {
        ((float4*)sW)[i] = gW[i];
        ((float4*)sD)[i] = gD[i];
    }
    __syncthreads();

    int tx = tid & 15, ty = tid >> 4;
    int t0 = ty * 8, n0 = tx * 8;
    float acc[8][8];
#pragma unroll
    for (int r = 0; r < 8; ++r)
#pragma unroll
        for (int c = 0; c < 8; ++c) acc[r][c] = 0.f;

#pragma unroll 4
    for (int k = 0; k < 128; ++k) {
        float4 w0 = *(const float4*)&sW[k * 128 + t0];
        float4 w1 = *(const float4*)&sW[k * 128 + t0 + 4];
        float4 d0 = *(const float4*)&sD[k * 128 + n0];
        float4 d1 = *(const float4*)&sD[k * 128 + n0 + 4];
        float w[8] = {w0.x, w0.y, w0.z, w0.w, w1.x, w1.y, w1.z, w1.w};
        float d[8] = {d0.x, d0.y, d0.z, d0.w, d1.x, d1.y, d1.z, d1.w};
#pragma unroll
        for (int r = 0; r < 8; ++r)
#pragma unroll
            for (int c = 0; c < 8; ++c) acc[r][c] += w[r] * d[c];
    }

    float* outp = g_preT + (size_t)b * (TT * NN);
#pragma unroll
    for (int r = 0; r < 8; ++r) {
        int t = t0 + r;
        float bt = __ldg(&b1[t]);
        float4 o0 = {acc[r][0] + bt, acc[r][1] + bt, acc[r][2] + bt, acc[r][3] + bt};
        float4 o1 = {acc[r][4] + bt, acc[r][5] + bt, acc[r][6] + bt, acc[r][7] + bt};
        *(float4*)&outp[t * 128 + n0] = o0;
        *(float4*)&outp[t * 128 + n0 + 4] = o1;
    }
}

// ---------------------------------------------------------------------------
// K2: xW[s][b][h] = data[b][s][:] @ Wx + bias.  M=T*B=65536, K=128, N=256.
// Grid (1024, 4): 64 rows x 64 cols per CTA. 16x16 threads, 4x4 reg tile.
// ---------------------------------------------------------------------------
__global__ __launch_bounds__(256) void k_xw(const float* __restrict__ data,
                                            const float* __restrict__ Wx,
                                            const float* __restrict__ bvec) {
    extern __shared__ float sm[];
    float* sA = sm;         // [64][128]  rows (b), cols k
    float* sB = sm + 8192;  // [128][64]  k, h
    int m0 = blockIdx.x * 64;  // m = s*512 + b
    int s = m0 >> 9;
    int b0 = m0 & 511;
    int h0 = blockIdx.y * 64;
    int tid = threadIdx.x;

    for (int i = tid; i < 2048; i += 256) {
        int r = i >> 5, k4 = i & 31;
        ((float4*)sA)[i] = *(const float4*)&data[(size_t)(b0 + r) * (TT * NN) + s * NN + k4 * 4];
    }
    for (int i = tid; i < 2048; i += 256) {
        int k = i >> 4, c4 = i & 15;
        ((float4*)sB)[i] = *(const float4*)&Wx[k * HH + h0 + c4 * 4];
    }
    __syncthreads();

    int tx = tid & 15, ty = tid >> 4;
    int r0 = ty * 4, c0 = tx * 4;
    float acc[4][4];
#pragma unroll
    for (int r = 0; r < 4; ++r)
#pragma unroll
        for (int c = 0; c < 4; ++c) acc[r][c] = 0.f;

#pragma unroll 4
    for (int k = 0; k < 128; ++k) {
        float a[4];
#pragma unroll
        for (int r = 0; r < 4; ++r) a[r] = sA[(r0 + r) * 128 + k];
        float4 bb = *(const float4*)&sB[k * 64 + c0];
        float bc[4] = {bb.x, bb.y, bb.z, bb.w};
#pragma unroll
        for (int r = 0; r < 4; ++r)
#pragma unroll
            for (int c = 0; c < 4; ++c) acc[r][c] += a[r] * bc[c];
    }

#pragma unroll
    for (int r = 0; r < 4; ++r) {
        float* o = g_xW + (size_t)s * (BB * HH) + (size_t)(b0 + r0 + r) * HH + h0 + c0;
#pragma unroll
        for (int c = 0; c < 4; ++c) o[c] = acc[r][c] + __ldg(&bvec[h0 + c0 + c]);
    }
}

// ---------------------------------------------------------------------------
// K3: recurrence. 128 CTAs, each owns 4 batch rows; loops all 128 steps
// locally (rows are independent -> no global sync). h kept in smem [k][r].
// Wh streamed from L1/L2 (256KB, mostly L1-resident).
// ---------------------------------------------------------------------------
__global__ __launch_bounds__(256) void k_rnn(const float* __restrict__ h0,
                                             const float* __restrict__ Wh) {
    __shared__ float sh[HH * 4];  // sh[k][r]
    int b0 = blockIdx.x * 4;
    int j = threadIdx.x;  // output column 0..255

#pragma unroll
    for (int r = 0; r < 4; ++r) sh[j * 4 + r] = h0[(size_t)(b0 + r) * HH + j];
    __syncthreads();

    for (int s = 0; s < TT; ++s) {
        const float* xw = g_xW + (size_t)s * (BB * HH) + (size_t)b0 * HH;
        float a0 = xw[j], a1 = xw[HH + j], a2 = xw[2 * HH + j], a3 = xw[3 * HH + j];
#pragma unroll 8
        for (int k = 0; k < HH; ++k) {
            float w = __ldg(&Wh[k * HH + j]);
            float4 hv = *(const float4*)&sh[k * 4];
            a0 += hv.x * w;
            a1 += hv.y * w;
            a2 += hv.z * w;
            a3 += hv.w * w;
        }
        a0 = tanhf(a0);
        a1 = tanhf(a1);
        a2 = tanhf(a2);
        a3 = tanhf(a3);
        __syncthreads();
        float4 nh = {a0, a1, a2, a3};
        *(float4*)&sh[j * 4] = nh;
        float* ho = g_Hs + (size_t)s * (BB * HH) + (size_t)b0 * HH;
        ho[j] = a0;
        ho[HH + j] = a1;
        ho[2 * HH + j] = a2;
        ho[3 * HH + j] = a3;
        __syncthreads();
    }
}

// ---------------------------------------------------------------------------
// K4: Q[s][b][t] = Hs[s][b][:] @ W2 + b2.  M=65536, K=256, N=128.
// 64 rows x 128 cols per CTA. smem: A 64KB + W2 128KB. 4x8 reg tile.
// ---------------------------------------------------------------------------
__global__ __launch_bounds__(256) void k_q(const float* __restrict__ W2,
                                           const float* __restrict__ b2) {
    extern __shared__ float sm[];
    float* sA = sm;          // [64][256]
    float* sB = sm + 16384;  // [256][128]
    int m0 = blockIdx.x * 64;
    int tid = threadIdx.x;

    const float4* gA = (const float4*)(g_Hs + (size_t)m0 * HH);
    for (int i = tid; i < 4096; i += 256) ((float4*)sA)[i] = gA[i];
    const float4* gB = (const float4*)W2;
    for (int i = tid; i < 8192; i += 256) ((float4*)sB)[i] = gB[i];
    __syncthreads();

    int tx = tid & 15, ty = tid >> 4;
    int r0 = ty * 4, c0 = tx * 8;
    float acc[4][8];
#pragma unroll
    for (int r = 0; r < 4; ++r)
#pragma unroll
        for (int c = 0; c < 8; ++c) acc[r][c] = 0.f;

#pragma unroll 4
    for (int k = 0; k < HH; ++k) {
        float a[4];
#pragma unroll
        for (int r = 0; r < 4; ++r) a[r] = sA[(r0 + r) * HH + k];
        float4 v0 = *(const float4*)&sB[k * 128 + c0];
        float4 v1 = *(const float4*)&sB[k * 128 + c0 + 4];
        float bc[8] = {v0.x, v0.y, v0.z, v0.w, v1.x, v1.y, v1.z, v1.w};
#pragma unroll
        for (int r = 0; r < 4; ++r)
#pragma unroll
            for (int c = 0; c < 8; ++c) acc[r][c] += a[r] * bc[c];
    }

#pragma unroll
    for (int r = 0; r < 4; ++r) {
        int m = m0 + r0 + r;
        float* qo = g_Q + (size_t)m * TT + c0;
#pragma unroll
        for (int c = 0; c < 8; ++c) qo[c] = acc[r][c] + __ldg(&b2[c0 + c]);
    }
}

// ---------------------------------------------------------------------------
// K5: attention scores + softmax + fused output multiply.
// One CTA per b; preT[b] resident in smem; 2 timesteps per iteration
// (128 threads each). alpha[s,b,n] -> out[4s + (b>>7), b&127, n].
// MUFU.TANH-bound by design.
// ---------------------------------------------------------------------------
__global__ __launch_bounds__(256) void k_att(const float* __restrict__ data,
                                             const float* __restrict__ Wv,
                                             float* __restrict__ out) {
    extern __shared__ float sm[];
    float* sP = sm;           // [128][128] sP[t][n]
    float* sQ = sm + 16384;   // [2][128]
    float* sWv = sQ + 256;    // [128]
    float* sred = sWv + 128;  // [8]
    int b = blockIdx.x;
    int tid = threadIdx.x;

    const float4* gP = (const float4*)(g_preT + (size_t)b * (TT * NN));
    for (int i = tid; i < 4096; i += 256) ((float4*)sP)[i] = gP[i];
    if (tid < 128) sWv[tid] = Wv[tid];
    __syncthreads();

    int n = tid & 127;
    int grp = tid >> 7;        // which of 2 timesteps this thread serves
    int lane = tid & 31;
    int wig = (tid >> 5) & 3;  // warp index within group

    for (int si = 0; si < 64; ++si) {
        int s = si * 2 + grp;
        sQ[tid] = g_Q[(size_t)s * (BB * TT) + b * TT + n];
        __syncthreads();

        const float* qrow = sQ + grp * 128;
        float e = 0.f;
#pragma unroll 8
        for (int t = 0; t < 128; ++t) {
            e += sWv[t] * tanh_fast(sP[t * 128 + n] + qrow[t]);
        }

        // softmax over n within the 128-thread group
        float mx = e;
#pragma unroll
        for (int o = 16; o; o >>= 1) mx = fmaxf(mx, __shfl_xor_sync(0xFFFFFFFFu, mx, o));
        if (lane == 0) sred[grp * 4 + wig] = mx;
        __syncthreads();
        mx = fmaxf(fmaxf(sred[grp * 4 + 0], sred[grp * 4 + 1]),
                   fmaxf(sred[grp * 4 + 2], sred[grp * 4 + 3]));
        float ex = __expf(e - mx);
        float sum = ex;
#pragma unroll
        for (int o = 16; o; o >>= 1) sum += __shfl_xor_sync(0xFFFFFFFFu, sum, o);
        __syncthreads();  // sred(max) reads done
        if (lane == 0) sred[grp * 4 + wig] = sum;
        __syncthreads();
        sum = sred[grp * 4 + 0] + sred[grp * 4 + 1] + sred[grp * 4 + 2] + sred[grp * 4 + 3];
        float alpha = ex / sum;

        // faithful-reshape index map: alpha[s,b,n] -> out[4s + b>>7, b&127, n]
        int bp = 4 * s + (b >> 7);
        int tp = b & 127;
        size_t idx = (size_t)bp * (TT * NN) + tp * NN + n;
        out[idx] = data[idx] * alpha;
        __syncthreads();  // protect sQ/sred before next iteration
    }
}

// ---------------------------------------------------------------------------
extern "C" void kernel_launch(void* const* d_in, const int* in_sizes, int n_in,
                              void* d_out, int out_size) {
    const float* data = (const float*)d_in[0];
    const float* h0 = (const float*)d_in[1];
    const float* Wx = (const float*)d_in[2];
    const float* Wh = (const float*)d_in[3];
    const float* bvec = (const float*)d_in[4];
    const float* W1 = (const float*)d_in[5];
    const float* b1 = (const float*)d_in[6];
    const float* W2 = (const float*)d_in[7];
    const float* b2 = (const float*)d_in[8];
    const float* Wv = (const float*)d_in[9];
    // d_in[10] = bv (softmax-invariant, skipped), d_in[11] = n (fixed 128)
    float* out = (float*)d_out;

    const int SM_PRE = 2 * 128 * 128 * 4;                    // 128 KB
    const int SM_XW = (64 * 128 + 128 * 64) * 4;             // 64 KB
    const int SM_Q = (64 * 256 + 256 * 128) * 4;             // 192 KB
    const int SM_ATT = (128 * 128 + 256 + 128 + 8) * 4;      // ~66 KB

    cudaFuncSetAttribute(k_pre, cudaFuncAttributeMaxDynamicSharedMemorySize, SM_PRE);
    cudaFuncSetAttribute(k_xw, cudaFuncAttributeMaxDynamicSharedMemorySize, SM_XW);
    cudaFuncSetAttribute(k_q, cudaFuncAttributeMaxDynamicSharedMemorySize, SM_Q);
    cudaFuncSetAttribute(k_att, cudaFuncAttributeMaxDynamicSharedMemorySize, SM_ATT);

    k_pre<<<BB, 256, SM_PRE>>>(data, W1, b1);
    k_xw<<<dim3((TT * BB) / 64, HH / 64), 256, SM_XW>>>(data, Wx, bvec);
    k_rnn<<<BB / 4, 256>>>(h0, Wh);
    k_q<<<(TT * BB) / 64, 256, SM_Q>>>(W2, b2);
    k_att<<<BB, 256, SM_ATT>>>(data, Wv, out);
}

// round 2
// speedup vs baseline: 1.3401x; 1.3401x over previous
#include <cuda_runtime.h>
#include <cuda_bf16.h>

// Shapes: B=512, T=128, N=128, H=256
#define BB 512
#define TT 128
#define NN 128
#define HH 256

__device__ float g_xW[TT * BB * HH];    // [s][b][h]
__device__ float g_Hs[TT * BB * HH];    // [s][b][h]
__device__ float g_Q[TT * BB * TT];     // [s][b][t]
__device__ float g_preT[BB * TT * NN];  // [b][t][n]

__device__ __forceinline__ float tanh_fast(float x) {
    float y;
    asm("tanh.approx.f32 %0, %1;" : "=f"(y) : "f"(x));
    return y;
}

// ---------------------------------------------------------------------------
// K_xw: xW[m][h] = data-row(m) @ Wx + b, m=s*512+b, K=128, N=256.
// 128x128 tile, Kc=16, double-buffered, 8x8 reg tile, 2 CTAs/SM.
// ---------------------------------------------------------------------------
__global__ __launch_bounds__(256, 2) void k_xw2(const float* __restrict__ data,
                                                const float* __restrict__ Wx,
                                                const float* __restrict__ bvec) {
    __shared__ float sA[2][16][132];  // [k][m], padded
    __shared__ float sB[2][16][128];  // [k][n]
    int m0 = blockIdx.x * 128;
    int h0 = blockIdx.y * 128;
    int tid = threadIdx.x;

    // A load: thread -> row am, 8 k-values starting at ak
    int am = tid >> 1;
    int ak = (tid & 1) * 8;
    int m = m0 + am;
    int s = m >> 9, b = m & 511;
    const float* aptr = data + (size_t)b * (TT * NN) + s * NN + ak;
    // B load: rows kb, kb+8; 4 cols at nb
    int kb = tid >> 5;
    int nb = (tid & 31) * 4;
    const float* bptr = Wx + (size_t)kb * HH + h0 + nb;

    float4 pa0 = *(const float4*)(aptr);
    float4 pa1 = *(const float4*)(aptr + 4);
    float4 pb0 = *(const float4*)(bptr);
    float4 pb1 = *(const float4*)(bptr + 8 * HH);
    {
        float av[8] = {pa0.x, pa0.y, pa0.z, pa0.w, pa1.x, pa1.y, pa1.z, pa1.w};
#pragma unroll
        for (int j = 0; j < 8; ++j) sA[0][ak + j][am] = av[j];
        *(float4*)&sB[0][kb][nb] = pb0;
        *(float4*)&sB[0][kb + 8][nb] = pb1;
    }
    __syncthreads();

    int ty = tid >> 4, tx = tid & 15;
    int mr = ty * 8, nr = tx * 8;
    float acc[8][8] = {};

#pragma unroll 2
    for (int c = 0; c < 8; ++c) {
        if (c + 1 < 8) {
            int k0 = (c + 1) * 16;
            pa0 = *(const float4*)(aptr + k0);
            pa1 = *(const float4*)(aptr + k0 + 4);
            pb0 = *(const float4*)(bptr + (size_t)k0 * HH);
            pb1 = *(const float4*)(bptr + (size_t)(k0 + 8) * HH);
        }
        int buf = c & 1;
#pragma unroll
        for (int k = 0; k < 16; ++k) {
            float4 a0 = *(const float4*)&sA[buf][k][mr];
            float4 a1 = *(const float4*)&sA[buf][k][mr + 4];
            float4 b0 = *(const float4*)&sB[buf][k][nr];
            float4 b1 = *(const float4*)&sB[buf][k][nr + 4];
            float av[8] = {a0.x, a0.y, a0.z, a0.w, a1.x, a1.y, a1.z, a1.w};
            float bv[8] = {b0.x, b0.y, b0.z, b0.w, b1.x, b1.y, b1.z, b1.w};
#pragma unroll
            for (int r = 0; r < 8; ++r)
#pragma unroll
                for (int cc = 0; cc < 8; ++cc) acc[r][cc] += av[r] * bv[cc];
        }
        if (c + 1 < 8) {
            int nbuf = (c + 1) & 1;
            float av[8] = {pa0.x, pa0.y, pa0.z, pa0.w, pa1.x, pa1.y, pa1.z, pa1.w};
#pragma unroll
            for (int j = 0; j < 8; ++j) sA[nbuf][ak + j][am] = av[j];
            *(float4*)&sB[nbuf][kb][nb] = pb0;
            *(float4*)&sB[nbuf][kb + 8][nb] = pb1;
            __syncthreads();
        }
    }

    float bias[8];
#pragma unroll
    for (int cc = 0; cc < 8; ++cc) bias[cc] = __ldg(&bvec[h0 + nr + cc]);
#pragma unroll
    for (int r = 0; r < 8; ++r) {
        float* o = g_xW + (size_t)(m0 + mr + r) * HH + h0 + nr;
        float4 o0 = {acc[r][0] + bias[0], acc[r][1] + bias[1], acc[r][2] + bias[2], acc[r][3] + bias[3]};
        float4 o1 = {acc[r][4] + bias[4], acc[r][5] + bias[5], acc[r][6] + bias[6], acc[r][7] + bias[7]};
        *(float4*)&o[0] = o0;
        *(float4*)&o[4] = o1;
    }
}

// ---------------------------------------------------------------------------
// K_q: Q[m][t] = Hs-row(m) @ W2 + b2, K=256, N=128 (single col tile).
// ---------------------------------------------------------------------------
__global__ __launch_bounds__(256, 2) void k_q2(const float* __restrict__ W2,
                                               const float* __restrict__ b2) {
    __shared__ float sA[2][16][132];
    __shared__ float sB[2][16][128];
    int m0 = blockIdx.x * 128;
    int tid = threadIdx.x;

    int am = tid >> 1;
    int ak = (tid & 1) * 8;
    const float* aptr = g_Hs + (size_t)(m0 + am) * HH + ak;
    int kb = tid >> 5;
    int nb = (tid & 31) * 4;
    const float* bptr = W2 + (size_t)kb * TT + nb;

    float4 pa0 = *(const float4*)(aptr);
    float4 pa1 = *(const float4*)(aptr + 4);
    float4 pb0 = *(const float4*)(bptr);
    float4 pb1 = *(const float4*)(bptr + 8 * TT);
    {
        float av[8] = {pa0.x, pa0.y, pa0.z, pa0.w, pa1.x, pa1.y, pa1.z, pa1.w};
#pragma unroll
        for (int j = 0; j < 8; ++j) sA[0][ak + j][am] = av[j];
        *(float4*)&sB[0][kb][nb] = pb0;
        *(float4*)&sB[0][kb + 8][nb] = pb1;
    }
    __syncthreads();

    int ty = tid >> 4, tx = tid & 15;
    int mr = ty * 8, nr = tx * 8;
    float acc[8][8] = {};

#pragma unroll 2
    for (int c = 0; c < 16; ++c) {
        if (c + 1 < 16) {
            int k0 = (c + 1) * 16;
            pa0 = *(const float4*)(aptr + k0);
            pa1 = *(const float4*)(aptr + k0 + 4);
            pb0 = *(const float4*)(bptr + (size_t)k0 * TT);
            pb1 = *(const float4*)(bptr + (size_t)(k0 + 8) * TT);
        }
        int buf = c & 1;
#pragma unroll
        for (int k = 0; k < 16; ++k) {
            float4 a0 = *(const float4*)&sA[buf][k][mr];
            float4 a1 = *(const float4*)&sA[buf][k][mr + 4];
            float4 b0 = *(const float4*)&sB[buf][k][nr];
            float4 b1 = *(const float4*)&sB[buf][k][nr + 4];
            float av[8] = {a0.x, a0.y, a0.z, a0.w, a1.x, a1.y, a1.z, a1.w};
            float bv[8] = {b0.x, b0.y, b0.z, b0.w, b1.x, b1.y, b1.z, b1.w};
#pragma unroll
            for (int r = 0; r < 8; ++r)
#pragma unroll
                for (int cc = 0; cc < 8; ++cc) acc[r][cc] += av[r] * bv[cc];
        }
        if (c + 1 < 16) {
            int nbuf = (c + 1) & 1;
            float av[8] = {pa0.x, pa0.y, pa0.z, pa0.w, pa1.x, pa1.y, pa1.z, pa1.w};
#pragma unroll
            for (int j = 0; j < 8; ++j) sA[nbuf][ak + j][am] = av[j];
            *(float4*)&sB[nbuf][kb][nb] = pb0;
            *(float4*)&sB[nbuf][kb + 8][nb] = pb1;
            __syncthreads();
        }
    }

    float bias[8];
#pragma unroll
    for (int cc = 0; cc < 8; ++cc) bias[cc] = __ldg(&b2[nr + cc]);
#pragma unroll
    for (int r = 0; r < 8; ++r) {
        float* o = g_Q + (size_t)(m0 + mr + r) * TT + nr;
        float4 o0 = {acc[r][0] + bias[0], acc[r][1] + bias[1], acc[r][2] + bias[2], acc[r][3] + bias[3]};
        float4 o1 = {acc[r][4] + bias[4], acc[r][5] + bias[5], acc[r][6] + bias[6], acc[r][7] + bias[7]};
        *(float4*)&o[0] = o0;
        *(float4*)&o[4] = o1;
    }
}

// ---------------------------------------------------------------------------
// K_pre: preT[b][t][n] = sum_tau W1[tau][t]*data[b][tau][n] + b1[t].
// Both operands are k-major (no transpose). One CTA per b, Kc=16 double-buf.
// ---------------------------------------------------------------------------
__global__ __launch_bounds__(256, 2) void k_pre2(const float* __restrict__ data,
                                                 const float* __restrict__ W1,
                                                 const float* __restrict__ b1) {
    __shared__ float sA[2][16][128];  // [tau][t]
    __shared__ float sB[2][16][128];  // [tau][n]
    int b = blockIdx.x;
    int tid = threadIdx.x;

    int kb = tid >> 5;
    int nb = (tid & 31) * 4;
    const float* aptr = W1 + (size_t)kb * TT + nb;
    const float* bptr = data + (size_t)b * (TT * NN) + (size_t)kb * NN + nb;

    float4 pa0 = *(const float4*)(aptr);
    float4 pa1 = *(const float4*)(aptr + 8 * TT);
    float4 pb0 = *(const float4*)(bptr);
    float4 pb1 = *(const float4*)(bptr + 8 * NN);
    *(float4*)&sA[0][kb][nb] = pa0;
    *(float4*)&sA[0][kb + 8][nb] = pa1;
    *(float4*)&sB[0][kb][nb] = pb0;
    *(float4*)&sB[0][kb + 8][nb] = pb1;
    __syncthreads();

    int ty = tid >> 4, tx = tid & 15;
    int mr = ty * 8, nr = tx * 8;
    float acc[8][8] = {};

#pragma unroll 2
    for (int c = 0; c < 8; ++c) {
        if (c + 1 < 8) {
            int k0 = (c + 1) * 16;
            pa0 = *(const float4*)(aptr + (size_t)k0 * TT);
            pa1 = *(const float4*)(aptr + (size_t)(k0 + 8) * TT);
            pb0 = *(const float4*)(bptr + (size_t)k0 * NN);
            pb1 = *(const float4*)(bptr + (size_t)(k0 + 8) * NN);
        }
        int buf = c & 1;
#pragma unroll
        for (int k = 0; k < 16; ++k) {
            float4 a0 = *(const float4*)&sA[buf][k][mr];
            float4 a1 = *(const float4*)&sA[buf][k][mr + 4];
            float4 b0 = *(const float4*)&sB[buf][k][nr];
            float4 b1 = *(const float4*)&sB[buf][k][nr + 4];
            float av[8] = {a0.x, a0.y, a0.z, a0.w, a1.x, a1.y, a1.z, a1.w};
            float bv[8] = {b0.x, b0.y, b0.z, b0.w, b1.x, b1.y, b1.z, b1.w};
#pragma unroll
            for (int r = 0; r < 8; ++r)
#pragma unroll
                for (int cc = 0; cc < 8; ++cc) acc[r][cc] += av[r] * bv[cc];
        }
        if (c + 1 < 8) {
            int nbuf = (c + 1) & 1;
            *(float4*)&sA[nbuf][kb][nb] = pa0;
            *(float4*)&sA[nbuf][kb + 8][nb] = pa1;
            *(float4*)&sB[nbuf][kb][nb] = pb0;
            *(float4*)&sB[nbuf][kb + 8][nb] = pb1;
            __syncthreads();
        }
    }

#pragma unroll
    for (int r = 0; r < 8; ++r) {
        int t = mr + r;
        float bt = __ldg(&b1[t]);
        float* o = g_preT + (size_t)b * (TT * NN) + (size_t)t * NN + nr;
        float4 o0 = {acc[r][0] + bt, acc[r][1] + bt, acc[r][2] + bt, acc[r][3] + bt};
        float4 o1 = {acc[r][4] + bt, acc[r][5] + bt, acc[r][6] + bt, acc[r][7] + bt};
        *(float4*)&o[0] = o0;
        *(float4*)&o[4] = o1;
    }
}

// ---------------------------------------------------------------------------
// K_rnn: 128 CTAs x 4 batch rows, all 128 steps local. First half of Wh
// cached in smem (128KB); second half streams through L1 (96KB available).
// ---------------------------------------------------------------------------
__global__ __launch_bounds__(256) void k_rnn2(const float* __restrict__ h0,
                                              const float* __restrict__ Wh) {
    extern __shared__ float sm[];
    float* sWh = sm;              // [128][256]
    float* sh = sm + 128 * 256;   // [256][4]
    int b0 = blockIdx.x * 4;
    int j = threadIdx.x;

    const float4* gw = (const float4*)Wh;
    float4* swv = (float4*)sWh;
    for (int i = j; i < 128 * 256 / 4; i += 256) swv[i] = gw[i];
#pragma unroll
    for (int r = 0; r < 4; ++r) sh[j * 4 + r] = h0[(size_t)(b0 + r) * HH + j];
    __syncthreads();

    for (int s = 0; s < TT; ++s) {
        const float* xw = g_xW + (size_t)s * (BB * HH) + (size_t)b0 * HH;
        float a0 = xw[j], a1 = xw[HH + j], a2 = xw[2 * HH + j], a3 = xw[3 * HH + j];
#pragma unroll 8
        for (int k = 0; k < 128; ++k) {
            float w = sWh[k * 256 + j];
            float4 hv = *(const float4*)&sh[k * 4];
            a0 += hv.x * w;
            a1 += hv.y * w;
            a2 += hv.z * w;
            a3 += hv.w * w;
        }
#pragma unroll 8
        for (int k = 128; k < 256; ++k) {
            float w = __ldg(&Wh[(size_t)k * HH + j]);
            float4 hv = *(const float4*)&sh[k * 4];
            a0 += hv.x * w;
            a1 += hv.y * w;
            a2 += hv.z * w;
            a3 += hv.w * w;
        }
        a0 = tanhf(a0);
        a1 = tanhf(a1);
        a2 = tanhf(a2);
        a3 = tanhf(a3);
        __syncthreads();
        *(float4*)&sh[j * 4] = make_float4(a0, a1, a2, a3);
        float* ho = g_Hs + (size_t)s * (BB * HH) + (size_t)b0 * HH;
        ho[j] = a0;
        ho[HH + j] = a1;
        ho[2 * HH + j] = a2;
        ho[3 * HH + j] = a3;
        __syncthreads();
    }
}

// ---------------------------------------------------------------------------
// K_att: scores + softmax (no max-sub; |e|<=sum|Wv|~5) + fused output mul.
// alpha[s,b,n] -> out[4s + (b>>7), b&127, n].
// ---------------------------------------------------------------------------
__global__ __launch_bounds__(256) void k_att2(const float* __restrict__ data,
                                              const float* __restrict__ Wv,
                                              float* __restrict__ out) {
    extern __shared__ float sm[];
    float* sP = sm;           // [128][128]
    float* sQ = sm + 16384;   // [2][128]
    float* sWv = sQ + 256;    // [128]
    float* sred = sWv + 128;  // [8]
    int b = blockIdx.x;
    int tid = threadIdx.x;

    const float4* gP = (const float4*)(g_preT + (size_t)b * (TT * NN));
    for (int i = tid; i < 4096; i += 256) ((float4*)sP)[i] = gP[i];
    if (tid < 128) sWv[tid] = Wv[tid];
    __syncthreads();

    int n = tid & 127;
    int grp = tid >> 7;
    int lane = tid & 31;
    int wig = (tid >> 5) & 3;

    for (int si = 0; si < 64; ++si) {
        int s = si * 2 + grp;
        sQ[tid] = g_Q[(size_t)s * (BB * TT) + b * TT + n];
        __syncthreads();

        const float* qrow = sQ + grp * 128;
        float e = 0.f;
#pragma unroll 8
        for (int t = 0; t < 128; ++t) {
            e += sWv[t] * tanh_fast(sP[t * 128 + n] + qrow[t]);
        }

        float ex = __expf(e);
        float sum = ex;
#pragma unroll
        for (int o = 16; o; o >>= 1) sum += __shfl_xor_sync(0xFFFFFFFFu, sum, o);
        if (lane == 0) sred[grp * 4 + wig] = sum;
        __syncthreads();
        sum = sred[grp * 4 + 0] + sred[grp * 4 + 1] + sred[grp * 4 + 2] + sred[grp * 4 + 3];
        float alpha = ex / sum;

        int bp = 4 * s + (b >> 7);
        int tp = b & 127;
        size_t idx = (size_t)bp * (TT * NN) + tp * NN + n;
        out[idx] = data[idx] * alpha;
        __syncthreads();
    }
}

// ---------------------------------------------------------------------------
extern "C" void kernel_launch(void* const* d_in, const int* in_sizes, int n_in,
                              void* d_out, int out_size) {
    const float* data = (const float*)d_in[0];
    const float* h0 = (const float*)d_in[1];
    const float* Wx = (const float*)d_in[2];
    const float* Wh = (const float*)d_in[3];
    const float* bvec = (const float*)d_in[4];
    const float* W1 = (const float*)d_in[5];
    const float* b1 = (const float*)d_in[6];
    const float* W2 = (const float*)d_in[7];
    const float* b2 = (const float*)d_in[8];
    const float* Wv = (const float*)d_in[9];
    float* out = (float*)d_out;

    const int SM_RNN = (128 * 256 + 256 * 4) * 4;        // 132 KB
    const int SM_ATT = (128 * 128 + 256 + 128 + 8) * 4;  // ~66 KB

    cudaFuncSetAttribute(k_rnn2, cudaFuncAttributeMaxDynamicSharedMemorySize, SM_RNN);
    cudaFuncSetAttribute(k_att2, cudaFuncAttributeMaxDynamicSharedMemorySize, SM_ATT);

    k_xw2<<<dim3((TT * BB) / 128, HH / 128), 256>>>(data, Wx, bvec);
    k_pre2<<<BB, 256>>>(data, W1, b1);
    k_rnn2<<<BB / 4, 256, SM_RNN>>>(h0, Wh);
    k_q2<<<(TT * BB) / 128, 256>>>(W2, b2);
    k_att2<<<BB, 256, SM_ATT>>>(data, Wv, out);
}

// round 3
// speedup vs baseline: 1.6073x; 1.1993x over previous
#include <cuda_runtime.h>
#include <cuda_bf16.h>

// Shapes: B=512, T=128, N=128, H=256
#define BB 512
#define TT 128
#define NN 128
#define HH 256

__device__ float g_xW[TT * BB * HH];    // [s][b][h]
__device__ float g_Hs[TT * BB * HH];    // [s][b][h]
__device__ float g_Q[TT * BB * TT];     // [s][b][t]
__device__ float g_preT[BB * TT * NN];  // [b][t][n]

__device__ __forceinline__ float tanh_fast(float x) {
    float y;
    asm("tanh.approx.f32 %0, %1;" : "=f"(y) : "f"(x));
    return y;
}

// ---------------------------------------------------------------------------
// K_xw: xW[m][h] = data-row(m) @ Wx + b, m=s*512+b, K=128, N=256.
// 128x128 tile, Kc=16, double-buffered, 8x8 reg tile, 2 CTAs/SM.
// ---------------------------------------------------------------------------
__global__ __launch_bounds__(256, 2) void k_xw2(const float* __restrict__ data,
                                                const float* __restrict__ Wx,
                                                const float* __restrict__ bvec) {
    __shared__ float sA[2][16][132];  // [k][m], padded
    __shared__ float sB[2][16][128];  // [k][n]
    int m0 = blockIdx.x * 128;
    int h0 = blockIdx.y * 128;
    int tid = threadIdx.x;

    int am = tid >> 1;
    int ak = (tid & 1) * 8;
    int m = m0 + am;
    int s = m >> 9, b = m & 511;
    const float* aptr = data + (size_t)b * (TT * NN) + s * NN + ak;
    int kb = tid >> 5;
    int nb = (tid & 31) * 4;
    const float* bptr = Wx + (size_t)kb * HH + h0 + nb;

    float4 pa0 = *(const float4*)(aptr);
    float4 pa1 = *(const float4*)(aptr + 4);
    float4 pb0 = *(const float4*)(bptr);
    float4 pb1 = *(const float4*)(bptr + 8 * HH);
    {
        float av[8] = {pa0.x, pa0.y, pa0.z, pa0.w, pa1.x, pa1.y, pa1.z, pa1.w};
#pragma unroll
        for (int j = 0; j < 8; ++j) sA[0][ak + j][am] = av[j];
        *(float4*)&sB[0][kb][nb] = pb0;
        *(float4*)&sB[0][kb + 8][nb] = pb1;
    }
    __syncthreads();

    int ty = tid >> 4, tx = tid & 15;
    int mr = ty * 8, nr = tx * 8;
    float acc[8][8] = {};

#pragma unroll 2
    for (int c = 0; c < 8; ++c) {
        if (c + 1 < 8) {
            int k0 = (c + 1) * 16;
            pa0 = *(const float4*)(aptr + k0);
            pa1 = *(const float4*)(aptr + k0 + 4);
            pb0 = *(const float4*)(bptr + (size_t)k0 * HH);
            pb1 = *(const float4*)(bptr + (size_t)(k0 + 8) * HH);
        }
        int buf = c & 1;
#pragma unroll
        for (int k = 0; k < 16; ++k) {
            float4 a0 = *(const float4*)&sA[buf][k][mr];
            float4 a1 = *(const float4*)&sA[buf][k][mr + 4];
            float4 b0 = *(const float4*)&sB[buf][k][nr];
            float4 b1 = *(const float4*)&sB[buf][k][nr + 4];
            float av[8] = {a0.x, a0.y, a0.z, a0.w, a1.x, a1.y, a1.z, a1.w};
            float bv[8] = {b0.x, b0.y, b0.z, b0.w, b1.x, b1.y, b1.z, b1.w};
#pragma unroll
            for (int r = 0; r < 8; ++r)
#pragma unroll
                for (int cc = 0; cc < 8; ++cc) acc[r][cc] += av[r] * bv[cc];
        }
        if (c + 1 < 8) {
            int nbuf = (c + 1) & 1;
            float av[8] = {pa0.x, pa0.y, pa0.z, pa0.w, pa1.x, pa1.y, pa1.z, pa1.w};
#pragma unroll
            for (int j = 0; j < 8; ++j) sA[nbuf][ak + j][am] = av[j];
            *(float4*)&sB[nbuf][kb][nb] = pb0;
            *(float4*)&sB[nbuf][kb + 8][nb] = pb1;
            __syncthreads();
        }
    }

    float bias[8];
#pragma unroll
    for (int cc = 0; cc < 8; ++cc) bias[cc] = __ldg(&bvec[h0 + nr + cc]);
#pragma unroll
    for (int r = 0; r < 8; ++r) {
        float* o = g_xW + (size_t)(m0 + mr + r) * HH + h0 + nr;
        float4 o0 = {acc[r][0] + bias[0], acc[r][1] + bias[1], acc[r][2] + bias[2], acc[r][3] + bias[3]};
        float4 o1 = {acc[r][4] + bias[4], acc[r][5] + bias[5], acc[r][6] + bias[6], acc[r][7] + bias[7]};
        *(float4*)&o[0] = o0;
        *(float4*)&o[4] = o1;
    }
}

// ---------------------------------------------------------------------------
// K_q: Q[m][t] = Hs-row(m) @ W2 + b2, K=256, N=128.
// ---------------------------------------------------------------------------
__global__ __launch_bounds__(256, 2) void k_q2(const float* __restrict__ W2,
                                               const float* __restrict__ b2) {
    __shared__ float sA[2][16][132];
    __shared__ float sB[2][16][128];
    int m0 = blockIdx.x * 128;
    int tid = threadIdx.x;

    int am = tid >> 1;
    int ak = (tid & 1) * 8;
    const float* aptr = g_Hs + (size_t)(m0 + am) * HH + ak;
    int kb = tid >> 5;
    int nb = (tid & 31) * 4;
    const float* bptr = W2 + (size_t)kb * TT + nb;

    float4 pa0 = *(const float4*)(aptr);
    float4 pa1 = *(const float4*)(aptr + 4);
    float4 pb0 = *(const float4*)(bptr);
    float4 pb1 = *(const float4*)(bptr + 8 * TT);
    {
        float av[8] = {pa0.x, pa0.y, pa0.z, pa0.w, pa1.x, pa1.y, pa1.z, pa1.w};
#pragma unroll
        for (int j = 0; j < 8; ++j) sA[0][ak + j][am] = av[j];
        *(float4*)&sB[0][kb][nb] = pb0;
        *(float4*)&sB[0][kb + 8][nb] = pb1;
    }
    __syncthreads();

    int ty = tid >> 4, tx = tid & 15;
    int mr = ty * 8, nr = tx * 8;
    float acc[8][8] = {};

#pragma unroll 2
    for (int c = 0; c < 16; ++c) {
        if (c + 1 < 16) {
            int k0 = (c + 1) * 16;
            pa0 = *(const float4*)(aptr + k0);
            pa1 = *(const float4*)(aptr + k0 + 4);
            pb0 = *(const float4*)(bptr + (size_t)k0 * TT);
            pb1 = *(const float4*)(bptr + (size_t)(k0 + 8) * TT);
        }
        int buf = c & 1;
#pragma unroll
        for (int k = 0; k < 16; ++k) {
            float4 a0 = *(const float4*)&sA[buf][k][mr];
            float4 a1 = *(const float4*)&sA[buf][k][mr + 4];
            float4 b0 = *(const float4*)&sB[buf][k][nr];
            float4 b1 = *(const float4*)&sB[buf][k][nr + 4];
            float av[8] = {a0.x, a0.y, a0.z, a0.w, a1.x, a1.y, a1.z, a1.w};
            float bv[8] = {b0.x, b0.y, b0.z, b0.w, b1.x, b1.y, b1.z, b1.w};
#pragma unroll
            for (int r = 0; r < 8; ++r)
#pragma unroll
                for (int cc = 0; cc < 8; ++cc) acc[r][cc] += av[r] * bv[cc];
        }
        if (c + 1 < 16) {
            int nbuf = (c + 1) & 1;
            float av[8] = {pa0.x, pa0.y, pa0.z, pa0.w, pa1.x, pa1.y, pa1.z, pa1.w};
#pragma unroll
            for (int j = 0; j < 8; ++j) sA[nbuf][ak + j][am] = av[j];
            *(float4*)&sB[nbuf][kb][nb] = pb0;
            *(float4*)&sB[nbuf][kb + 8][nb] = pb1;
            __syncthreads();
        }
    }

    float bias[8];
#pragma unroll
    for (int cc = 0; cc < 8; ++cc) bias[cc] = __ldg(&b2[nr + cc]);
#pragma unroll
    for (int r = 0; r < 8; ++r) {
        float* o = g_Q + (size_t)(m0 + mr + r) * TT + nr;
        float4 o0 = {acc[r][0] + bias[0], acc[r][1] + bias[1], acc[r][2] + bias[2], acc[r][3] + bias[3]};
        float4 o1 = {acc[r][4] + bias[4], acc[r][5] + bias[5], acc[r][6] + bias[6], acc[r][7] + bias[7]};
        *(float4*)&o[0] = o0;
        *(float4*)&o[4] = o1;
    }
}

// ---------------------------------------------------------------------------
// K_pre: preT[b][t][n] = sum_tau W1[tau][t]*data[b][tau][n] + b1[t].
// ---------------------------------------------------------------------------
__global__ __launch_bounds__(256, 2) void k_pre2(const float* __restrict__ data,
                                                 const float* __restrict__ W1,
                                                 const float* __restrict__ b1) {
    __shared__ float sA[2][16][128];
    __shared__ float sB[2][16][128];
    int b = blockIdx.x;
    int tid = threadIdx.x;

    int kb = tid >> 5;
    int nb = (tid & 31) * 4;
    const float* aptr = W1 + (size_t)kb * TT + nb;
    const float* bptr = data + (size_t)b * (TT * NN) + (size_t)kb * NN + nb;

    float4 pa0 = *(const float4*)(aptr);
    float4 pa1 = *(const float4*)(aptr + 8 * TT);
    float4 pb0 = *(const float4*)(bptr);
    float4 pb1 = *(const float4*)(bptr + 8 * NN);
    *(float4*)&sA[0][kb][nb] = pa0;
    *(float4*)&sA[0][kb + 8][nb] = pa1;
    *(float4*)&sB[0][kb][nb] = pb0;
    *(float4*)&sB[0][kb + 8][nb] = pb1;
    __syncthreads();

    int ty = tid >> 4, tx = tid & 15;
    int mr = ty * 8, nr = tx * 8;
    float acc[8][8] = {};

#pragma unroll 2
    for (int c = 0; c < 8; ++c) {
        if (c + 1 < 8) {
            int k0 = (c + 1) * 16;
            pa0 = *(const float4*)(aptr + (size_t)k0 * TT);
            pa1 = *(const float4*)(aptr + (size_t)(k0 + 8) * TT);
            pb0 = *(const float4*)(bptr + (size_t)k0 * NN);
            pb1 = *(const float4*)(bptr + (size_t)(k0 + 8) * NN);
        }
        int buf = c & 1;
#pragma unroll
        for (int k = 0; k < 16; ++k) {
            float4 a0 = *(const float4*)&sA[buf][k][mr];
            float4 a1 = *(const float4*)&sA[buf][k][mr + 4];
            float4 b0 = *(const float4*)&sB[buf][k][nr];
            float4 b1 = *(const float4*)&sB[buf][k][nr + 4];
            float av[8] = {a0.x, a0.y, a0.z, a0.w, a1.x, a1.y, a1.z, a1.w};
            float bv[8] = {b0.x, b0.y, b0.z, b0.w, b1.x, b1.y, b1.z, b1.w};
#pragma unroll
            for (int r = 0; r < 8; ++r)
#pragma unroll
                for (int cc = 0; cc < 8; ++cc) acc[r][cc] += av[r] * bv[cc];
        }
        if (c + 1 < 8) {
            int nbuf = (c + 1) & 1;
            *(float4*)&sA[nbuf][kb][nb] = pa0;
            *(float4*)&sA[nbuf][kb + 8][nb] = pa1;
            *(float4*)&sB[nbuf][kb][nb] = pb0;
            *(float4*)&sB[nbuf][kb + 8][nb] = pb1;
            __syncthreads();
        }
    }

#pragma unroll
    for (int r = 0; r < 8; ++r) {
        int t = mr + r;
        float bt = __ldg(&b1[t]);
        float* o = g_preT + (size_t)b * (TT * NN) + (size_t)t * NN + nr;
        float4 o0 = {acc[r][0] + bt, acc[r][1] + bt, acc[r][2] + bt, acc[r][3] + bt};
        float4 o1 = {acc[r][4] + bt, acc[r][5] + bt, acc[r][6] + bt, acc[r][7] + bt};
        *(float4*)&o[0] = o0;
        *(float4*)&o[4] = o1;
    }
}

// ---------------------------------------------------------------------------
// K_rnn3: 128 CTAs x 4 rows, 512 threads (split-K). kh=0 half: k<128 from
// smem-cached Wh; kh=1 half: k>=128 via LDG (L1/L2). Partials combined via
// smem reduction. 16 warps/SM hides LDG latency. h double-buffered in smem.
// ---------------------------------------------------------------------------
__global__ __launch_bounds__(512) void k_rnn3(const float* __restrict__ h0,
                                              const float* __restrict__ Wh) {
    extern __shared__ float sm[];
    float* sWh = sm;                  // [128][256]
    float* sh = sm + 128 * 256;       // [2][256][4]
    float* sred = sh + 2048;          // [256][4]
    int b0 = blockIdx.x * 4;
    int tid = threadIdx.x;
    int j = tid & 255;
    int kh = tid >> 8;

    {
        const float4* gw = (const float4*)Wh;
        float4* sw = (float4*)sWh;
        for (int i = tid; i < 128 * 256 / 4; i += 512) sw[i] = gw[i];
    }
    if (kh == 0) {
        float4 h4;
        h4.x = h0[(size_t)(b0 + 0) * HH + j];
        h4.y = h0[(size_t)(b0 + 1) * HH + j];
        h4.z = h0[(size_t)(b0 + 2) * HH + j];
        h4.w = h0[(size_t)(b0 + 3) * HH + j];
        *(float4*)&sh[j * 4] = h4;
    }
    __syncthreads();

    const float* wg = Wh + (size_t)128 * HH + j;  // streamed half

    for (int s = 0; s < TT; ++s) {
        int cur = (s & 1) * 1024;
        int nxt = 1024 - cur;
        const float* shc = sh + cur;
        float a0, a1, a2, a3;
        if (kh == 0) {
            const float* xw = g_xW + (size_t)s * (BB * HH) + (size_t)b0 * HH + j;
            a0 = xw[0];
            a1 = xw[HH];
            a2 = xw[2 * HH];
            a3 = xw[3 * HH];
            const float* wj = sWh + j;
#pragma unroll 8
            for (int k = 0; k < 128; ++k) {
                float w = wj[k * 256];
                float4 hv = *(const float4*)&shc[k * 4];
                a0 += hv.x * w;
                a1 += hv.y * w;
                a2 += hv.z * w;
                a3 += hv.w * w;
            }
        } else {
            a0 = a1 = a2 = a3 = 0.f;
#pragma unroll 8
            for (int k = 0; k < 128; ++k) {
                float w = __ldg(&wg[(size_t)k * HH]);
                float4 hv = *(const float4*)&shc[(k + 128) * 4];
                a0 += hv.x * w;
                a1 += hv.y * w;
                a2 += hv.z * w;
                a3 += hv.w * w;
            }
            *(float4*)&sred[j * 4] = make_float4(a0, a1, a2, a3);
        }
        __syncthreads();
        if (kh == 0) {
            float4 p = *(const float4*)&sred[j * 4];
            a0 = tanhf(a0 + p.x);
            a1 = tanhf(a1 + p.y);
            a2 = tanhf(a2 + p.z);
            a3 = tanhf(a3 + p.w);
            *(float4*)&sh[nxt + j * 4] = make_float4(a0, a1, a2, a3);
            float* ho = g_Hs + (size_t)s * (BB * HH) + (size_t)b0 * HH + j;
            ho[0] = a0;
            ho[HH] = a1;
            ho[2 * HH] = a2;
            ho[3 * HH] = a3;
        }
        __syncthreads();
    }
}

// ---------------------------------------------------------------------------
// K_att3: grid 1024 = (b, s-half). 32 s-iterations per CTA for wave balance.
// scores + softmax (no max-sub; |e| <= sum|Wv| ~ 5) + fused output multiply.
// alpha[s,b,n] -> out[4s + (b>>7), b&127, n].
// ---------------------------------------------------------------------------
__global__ __launch_bounds__(256) void k_att3(const float* __restrict__ data,
                                              const float* __restrict__ Wv,
                                              float* __restrict__ out) {
    extern __shared__ float sm[];
    float* sP = sm;           // [128][128]
    float* sQ = sm + 16384;   // [2][128]
    float* sWv = sQ + 256;    // [128]
    float* sred = sWv + 128;  // [8]
    int b = blockIdx.x >> 1;
    int shalf = blockIdx.x & 1;
    int tid = threadIdx.x;

    const float4* gP = (const float4*)(g_preT + (size_t)b * (TT * NN));
    for (int i = tid; i < 4096; i += 256) ((float4*)sP)[i] = gP[i];
    if (tid < 128) sWv[tid] = Wv[tid];
    __syncthreads();

    int n = tid & 127;
    int grp = tid >> 7;
    int lane = tid & 31;
    int wig = (tid >> 5) & 3;

    for (int si = 0; si < 32; ++si) {
        int s = shalf * 64 + si * 2 + grp;
        sQ[tid] = g_Q[(size_t)s * (BB * TT) + b * TT + n];
        __syncthreads();

        const float* qrow = sQ + grp * 128;
        float e = 0.f;
#pragma unroll 8
        for (int t = 0; t < 128; ++t) {
            e += sWv[t] * tanh_fast(sP[t * 128 + n] + qrow[t]);
        }

        float ex = __expf(e);
        float sum = ex;
#pragma unroll
        for (int o = 16; o; o >>= 1) sum += __shfl_xor_sync(0xFFFFFFFFu, sum, o);
        if (lane == 0) sred[grp * 4 + wig] = sum;
        __syncthreads();
        sum = sred[grp * 4 + 0] + sred[grp * 4 + 1] + sred[grp * 4 + 2] + sred[grp * 4 + 3];
        float alpha = ex / sum;

        int bp = 4 * s + (b >> 7);
        int tp = b & 127;
        size_t idx = (size_t)bp * (TT * NN) + tp * NN + n;
        out[idx] = data[idx] * alpha;
        __syncthreads();
    }
}

// ---------------------------------------------------------------------------
extern "C" void kernel_launch(void* const* d_in, const int* in_sizes, int n_in,
                              void* d_out, int out_size) {
    const float* data = (const float*)d_in[0];
    const float* h0 = (const float*)d_in[1];
    const float* Wx = (const float*)d_in[2];
    const float* Wh = (const float*)d_in[3];
    const float* bvec = (const float*)d_in[4];
    const float* W1 = (const float*)d_in[5];
    const float* b1 = (const float*)d_in[6];
    const float* W2 = (const float*)d_in[7];
    const float* b2 = (const float*)d_in[8];
    const float* Wv = (const float*)d_in[9];
    float* out = (float*)d_out;

    const int SM_RNN = (128 * 256 + 2 * 1024 + 1024) * 4;  // 140 KB
    const int SM_ATT = (128 * 128 + 256 + 128 + 8) * 4;    // ~66 KB

    cudaFuncSetAttribute(k_rnn3, cudaFuncAttributeMaxDynamicSharedMemorySize, SM_RNN);
    cudaFuncSetAttribute(k_att3, cudaFuncAttributeMaxDynamicSharedMemorySize, SM_ATT);

    k_xw2<<<dim3((TT * BB) / 128, HH / 128), 256>>>(data, Wx, bvec);
    k_pre2<<<BB, 256>>>(data, W1, b1);
    k_rnn3<<<BB / 4, 512, SM_RNN>>>(h0, Wh);
    k_q2<<<(TT * BB) / 128, 256>>>(W2, b2);
    k_att3<<<BB * 2, 256, SM_ATT>>>(data, Wv, out);
}